// round 14
// baseline (speedup 1.0000x reference)
#include <cuda_runtime.h>

// SpinorBilinears: psi [B=8, N=65536, S=4] f32, gamma [C=8, 4, 4] f32.
// Outputs flat in d_out: K0 [BN] | K1 [BN,8,8] | K2 [BN,8,8]
//   u_c = gamma_c^T p,  v_c = gamma_c p
//   K1[c][d] = 0.5*(u_c.v_d - u_d.v_c),  K2[c][d] = 0.5*(u_c.v_d + u_d.v_c)
//
// R11 structure (smem gamma, warp-private swizzled staging, __syncwarp only,
// __stcs evict-first streaming stores) made PERSISTENT: 5 blocks/SM x 148 SMs,
// grid-stride over token tiles. gamma loaded once per block; next tile's psi
// prefetched before the current tile's store phase (load latency hidden under
// ~20us of store work per iteration).

#define TPB 128
#define NTILES_TOTAL 4096       // BN / TPB for BN = 524288

__device__ __forceinline__ float dot4(const float* a, const float* b) {
    return fmaf(a[0], b[0], fmaf(a[1], b[1], fmaf(a[2], b[2], a[3] * b[3])));
}

__device__ __forceinline__ int swz(int e4, int l) {   // float4-index swizzle
    return (e4 & 8) | ((e4 & 7) ^ (l & 7));
}

__global__ __launch_bounds__(TPB, 5) void spinor_bilinears_kernel(
    const float4* __restrict__ psi4,
    const float4* __restrict__ gamma4,
    float* __restrict__ out,
    int BN)
{
    __shared__ float4 sg[32];             // gamma: 8 matrices x 4 rows
    __shared__ float4 stage4[4][512];     // 8 KB per warp

    const int tid  = threadIdx.x;
    const int warp = tid >> 5;
    const int l    = tid & 31;

    if (tid < 32) sg[tid] = __ldg(gamma4 + tid);
    __syncthreads();                      // once per block, before the loop

    const int    ntiles = BN / TPB;
    const int    stride = gridDim.x;
    const size_t bn     = (size_t)BN;

    // prefetch first tile's psi
    int    tile   = blockIdx.x;
    float4 p_next = (tile < ntiles) ? __ldg(psi4 + tile * TPB + tid)
                                    : make_float4(0.f, 0.f, 0.f, 0.f);

    for (; tile < ntiles; tile += stride) {
        const float4 p4 = p_next;
        const int nxt = tile + stride;
        if (nxt < ntiles) p_next = __ldg(psi4 + nxt * TPB + tid);

        const int t = tile * TPB + tid;         // this thread's token
        const float p[4] = {p4.x, p4.y, p4.z, p4.w};

        // K0 (coalesced streaming STG.32)
        __stcs(out + t, dot4(p, p));

        // u_c = gamma_c^T p ; v_c = gamma_c p  (broadcast LDS)
        float u[8][4], v[8][4];
#pragma unroll
        for (int c = 0; c < 8; c++) {
            const float4 r0 = sg[c * 4 + 0];
            const float4 r1 = sg[c * 4 + 1];
            const float4 r2 = sg[c * 4 + 2];
            const float4 r3 = sg[c * 4 + 3];
            v[c][0] = fmaf(r0.x, p[0], fmaf(r0.y, p[1], fmaf(r0.z, p[2], r0.w * p[3])));
            v[c][1] = fmaf(r1.x, p[0], fmaf(r1.y, p[1], fmaf(r1.z, p[2], r1.w * p[3])));
            v[c][2] = fmaf(r2.x, p[0], fmaf(r2.y, p[1], fmaf(r2.z, p[2], r2.w * p[3])));
            v[c][3] = fmaf(r3.x, p[0], fmaf(r3.y, p[1], fmaf(r3.z, p[2], r3.w * p[3])));
            u[c][0] = fmaf(r0.x, p[0], fmaf(r1.x, p[1], fmaf(r2.x, p[2], r3.x * p[3])));
            u[c][1] = fmaf(r0.y, p[0], fmaf(r1.y, p[1], fmaf(r2.y, p[2], r3.y * p[3])));
            u[c][2] = fmaf(r0.z, p[0], fmaf(r1.z, p[1], fmaf(r2.z, p[2], r3.z * p[3])));
            u[c][3] = fmaf(r0.w, p[0], fmaf(r1.w, p[1], fmaf(r2.w, p[2], r3.w * p[3])));
        }

        const int t0 = tile * TPB + warp * 32;  // warp's first token this tile
        float4* __restrict__ k1dst =
            reinterpret_cast<float4*>(out + bn) + (size_t)t0 * 16;
        float4* __restrict__ k2dst =
            reinterpret_cast<float4*>(out + bn + bn * 64) + (size_t)t0 * 16;

        // ================= K1 (antisymmetric) =================
#pragma unroll
        for (int c = 0; c < 8; c++) {
#pragma unroll
            for (int d4 = 0; d4 < 2; d4++) {
                const int d = d4 * 4;
                float4 r;
                r.x = 0.5f * (dot4(u[c], v[d + 0]) - dot4(u[d + 0], v[c]));
                r.y = 0.5f * (dot4(u[c], v[d + 1]) - dot4(u[d + 1], v[c]));
                r.z = 0.5f * (dot4(u[c], v[d + 2]) - dot4(u[d + 2], v[c]));
                r.w = 0.5f * (dot4(u[c], v[d + 3]) - dot4(u[d + 3], v[c]));
                stage4[warp][l * 16 + swz(c * 2 + d4, l)] = r;
            }
        }
        __syncwarp();
#pragma unroll
        for (int i = 0; i < 16; i++) {
            const int f4  = i * 32 + l;
            const int tok = f4 >> 4;
            const int e4  = f4 & 15;
            __stcs(&k1dst[f4], stage4[warp][tok * 16 + swz(e4, tok)]);
        }
        __syncwarp();

        // ================= K2 (symmetric) =================
#pragma unroll
        for (int c = 0; c < 8; c++) {
#pragma unroll
            for (int d4 = 0; d4 < 2; d4++) {
                const int d = d4 * 4;
                float4 r;
                r.x = 0.5f * (dot4(u[c], v[d + 0]) + dot4(u[d + 0], v[c]));
                r.y = 0.5f * (dot4(u[c], v[d + 1]) + dot4(u[d + 1], v[c]));
                r.z = 0.5f * (dot4(u[c], v[d + 2]) + dot4(u[d + 2], v[c]));
                r.w = 0.5f * (dot4(u[c], v[d + 3]) + dot4(u[d + 3], v[c]));
                stage4[warp][l * 16 + swz(c * 2 + d4, l)] = r;
            }
        }
        __syncwarp();
#pragma unroll
        for (int i = 0; i < 16; i++) {
            const int f4  = i * 32 + l;
            const int tok = f4 >> 4;
            const int e4  = f4 & 15;
            __stcs(&k2dst[f4], stage4[warp][tok * 16 + swz(e4, tok)]);
        }
        __syncwarp();
    }
}

extern "C" void kernel_launch(void* const* d_in, const int* in_sizes, int n_in,
                              void* d_out, int out_size) {
    const float4* psi4   = (const float4*)d_in[0];   // [B, N, 4] f32
    const float4* gamma4 = (const float4*)d_in[1];   // [8, 4, 4] f32
    float* out = (float*)d_out;

    const int BN = in_sizes[0] / 4;                  // 524288 tokens

    // persistent grid: 5 resident blocks/SM x 148 SMs
    const int grid = 740;

    spinor_bilinears_kernel<<<grid, TPB>>>(psi4, gamma4, out, BN);
}

// round 15
// speedup vs baseline: 1.0336x; 1.0336x over previous
#include <cuda_runtime.h>

// SpinorBilinears: psi [B=8, N=65536, S=4] f32, gamma [C=8, 4, 4] f32.
// Outputs flat in d_out: K0 [BN] | K1 [BN,8,8] | K2 [BN,8,8]
//   u_c = gamma_c^T p,  v_c = gamma_c p
//   K1[c][d] = 0.5*(u_c.v_d - u_d.v_c),  K2[c][d] = 0.5*(u_c.v_d + u_d.v_c)
//
// R9 winner (best measured: block-swizzled staging + __stcs streaming stores,
// wave-launched grid for dense in-flight write windows) + __ldcs evict-first
// psi loads so the 8 MB read stream doesn't occupy L2 capacity needed for
// write coalescing.

#define TPB 128

__device__ __forceinline__ float dot4(const float* a, const float* b) {
    return fmaf(a[0], b[0], fmaf(a[1], b[1], fmaf(a[2], b[2], a[3] * b[3])));
}

__global__ __launch_bounds__(TPB) void spinor_bilinears_kernel(
    const float4* __restrict__ psi4,
    const float4* __restrict__ gamma4,
    float* __restrict__ out,
    int BN)
{
    __shared__ float4 sg[32];            // gamma: 8 matrices x 4 rows, as float4
    __shared__ float  stage[TPB * 64];   // 32 KB staging for one [128 tokens x 64] matrix

    const int tid = threadIdx.x;
    if (tid < 32) sg[tid] = __ldg(gamma4 + tid);
    __syncthreads();

    const int t = blockIdx.x * TPB + tid;   // token id; grid sized exactly BN/TPB

    // ---- load spinor (evict-first: don't pollute L2 against the write stream) ----
    const float4 p4 = __ldcs(psi4 + t);
    const float p[4] = {p4.x, p4.y, p4.z, p4.w};

    // ---- K0 (coalesced streaming STG.32) ----
    __stcs(out + t, dot4(p, p));

    // ---- u_c = gamma_c^T p ; v_c = gamma_c p ----
    float u[8][4], v[8][4];
#pragma unroll
    for (int c = 0; c < 8; c++) {
        const float4 r0 = sg[c * 4 + 0];
        const float4 r1 = sg[c * 4 + 1];
        const float4 r2 = sg[c * 4 + 2];
        const float4 r3 = sg[c * 4 + 3];
        v[c][0] = fmaf(r0.x, p[0], fmaf(r0.y, p[1], fmaf(r0.z, p[2], r0.w * p[3])));
        v[c][1] = fmaf(r1.x, p[0], fmaf(r1.y, p[1], fmaf(r1.z, p[2], r1.w * p[3])));
        v[c][2] = fmaf(r2.x, p[0], fmaf(r2.y, p[1], fmaf(r2.z, p[2], r2.w * p[3])));
        v[c][3] = fmaf(r3.x, p[0], fmaf(r3.y, p[1], fmaf(r3.z, p[2], r3.w * p[3])));
        u[c][0] = fmaf(r0.x, p[0], fmaf(r1.x, p[1], fmaf(r2.x, p[2], r3.x * p[3])));
        u[c][1] = fmaf(r0.y, p[0], fmaf(r1.y, p[1], fmaf(r2.y, p[2], r3.y * p[3])));
        u[c][2] = fmaf(r0.z, p[0], fmaf(r1.z, p[1], fmaf(r2.z, p[2], r3.z * p[3])));
        u[c][3] = fmaf(r0.w, p[0], fmaf(r1.w, p[1], fmaf(r2.w, p[2], r3.w * p[3])));
    }

    const size_t bn      = (size_t)BN;
    const size_t blkBase = (size_t)blockIdx.x * (size_t)(TPB * 64);
    const int    sw      = tid & 15;     // float4-granular XOR swizzle key

    // ================= K1 (antisymmetric) =================
#pragma unroll
    for (int c = 0; c < 8; c++) {
#pragma unroll
        for (int d4 = 0; d4 < 2; d4++) {
            float4 row;
            {
                const int d = d4 * 4;
                row.x = 0.5f * (dot4(u[c], v[d + 0]) - dot4(u[d + 0], v[c]));
                row.y = 0.5f * (dot4(u[c], v[d + 1]) - dot4(u[d + 1], v[c]));
                row.z = 0.5f * (dot4(u[c], v[d + 2]) - dot4(u[d + 2], v[c]));
                row.w = 0.5f * (dot4(u[c], v[d + 3]) - dot4(u[d + 3], v[c]));
            }
            const int e4 = c * 2 + d4;                              // 0..15
            *reinterpret_cast<float4*>(&stage[tid * 64 + ((e4 ^ sw) << 2)]) = row;
        }
    }
    __syncthreads();

    {
        float* __restrict__ dst = out + bn + blkBase;
#pragma unroll
        for (int it = 0; it < 16; it++) {
            const int o   = it * (TPB * 4) + tid * 4;   // float offset in block's 8192-float region
            const int tok = o >> 6;
            const int e4  = (o >> 2) & 15;
            const float4 val =
                *reinterpret_cast<const float4*>(&stage[tok * 64 + ((e4 ^ (tok & 15)) << 2)]);
            __stcs(reinterpret_cast<float4*>(&dst[o]), val);
        }
    }
    __syncthreads();

    // ================= K2 (symmetric) =================
#pragma unroll
    for (int c = 0; c < 8; c++) {
#pragma unroll
        for (int d4 = 0; d4 < 2; d4++) {
            float4 row;
            {
                const int d = d4 * 4;
                row.x = 0.5f * (dot4(u[c], v[d + 0]) + dot4(u[d + 0], v[c]));
                row.y = 0.5f * (dot4(u[c], v[d + 1]) + dot4(u[d + 1], v[c]));
                row.z = 0.5f * (dot4(u[c], v[d + 2]) + dot4(u[d + 2], v[c]));
                row.w = 0.5f * (dot4(u[c], v[d + 3]) + dot4(u[d + 3], v[c]));
            }
            const int e4 = c * 2 + d4;
            *reinterpret_cast<float4*>(&stage[tid * 64 + ((e4 ^ sw) << 2)]) = row;
        }
    }
    __syncthreads();

    {
        float* __restrict__ dst = out + bn + bn * 64 + blkBase;
#pragma unroll
        for (int it = 0; it < 16; it++) {
            const int o   = it * (TPB * 4) + tid * 4;
            const int tok = o >> 6;
            const int e4  = (o >> 2) & 15;
            const float4 val =
                *reinterpret_cast<const float4*>(&stage[tok * 64 + ((e4 ^ (tok & 15)) << 2)]);
            __stcs(reinterpret_cast<float4*>(&dst[o]), val);
        }
    }
}

extern "C" void kernel_launch(void* const* d_in, const int* in_sizes, int n_in,
                              void* d_out, int out_size) {
    const float4* psi4   = (const float4*)d_in[0];   // [B, N, 4] f32
    const float4* gamma4 = (const float4*)d_in[1];   // [8, 4, 4] f32
    float* out = (float*)d_out;

    const int BN = in_sizes[0] / 4;                  // 524288 tokens
    const int grid = BN / TPB;                       // 4096, exact

    spinor_bilinears_kernel<<<grid, TPB>>>(psi4, gamma4, out, BN);
}

// round 16
// speedup vs baseline: 1.1377x; 1.1007x over previous
#include <cuda_runtime.h>

// SpinorBilinears: psi [B=8, N=65536, S=4] f32, gamma [C=8, 4, 4] f32.
// Outputs flat in d_out: K0 [BN] | K1 [BN,8,8] | K2 [BN,8,8]
//   u_c = gamma_c^T p,  v_c = gamma_c p
//   K1[c][d] = 0.5*(u_c.v_d - u_d.v_c),  K2[c][d] = 0.5*(u_c.v_d + u_d.v_c)
//
// FINAL (R9 winner, best measured 43.46us): one thread per token, smem gamma,
// block-level XOR-swizzled staging -> fully coalesced STG.128, __stcs
// evict-first streaming on all output stores (the single change that beat the
// plateau), __ldg psi (stays L2-resident across graph replays), wave-launched
// grid (dense in-flight write windows for DRAM page locality).
// Effective write stream ~6.2 TB/s (~78% of HBM spec) == practical ceiling
// for this pure-write workload; all other axes tested and neutral/regressive.

#define TPB 128

__device__ __forceinline__ float dot4(const float* a, const float* b) {
    return fmaf(a[0], b[0], fmaf(a[1], b[1], fmaf(a[2], b[2], a[3] * b[3])));
}

__global__ __launch_bounds__(TPB) void spinor_bilinears_kernel(
    const float4* __restrict__ psi4,
    const float4* __restrict__ gamma4,
    float* __restrict__ out,
    int BN)
{
    __shared__ float4 sg[32];            // gamma: 8 matrices x 4 rows, as float4
    __shared__ float  stage[TPB * 64];   // 32 KB staging for one [128 tokens x 64] matrix

    const int tid = threadIdx.x;
    if (tid < 32) sg[tid] = __ldg(gamma4 + tid);
    __syncthreads();

    const int t = blockIdx.x * TPB + tid;   // token id; grid sized exactly BN/TPB

    // ---- load spinor (L2-resident across replays) ----
    const float4 p4 = __ldg(psi4 + t);
    const float p[4] = {p4.x, p4.y, p4.z, p4.w};

    // ---- K0 (coalesced streaming STG.32) ----
    __stcs(out + t, dot4(p, p));

    // ---- u_c = gamma_c^T p ; v_c = gamma_c p ----
    float u[8][4], v[8][4];
#pragma unroll
    for (int c = 0; c < 8; c++) {
        const float4 r0 = sg[c * 4 + 0];
        const float4 r1 = sg[c * 4 + 1];
        const float4 r2 = sg[c * 4 + 2];
        const float4 r3 = sg[c * 4 + 3];
        v[c][0] = fmaf(r0.x, p[0], fmaf(r0.y, p[1], fmaf(r0.z, p[2], r0.w * p[3])));
        v[c][1] = fmaf(r1.x, p[0], fmaf(r1.y, p[1], fmaf(r1.z, p[2], r1.w * p[3])));
        v[c][2] = fmaf(r2.x, p[0], fmaf(r2.y, p[1], fmaf(r2.z, p[2], r2.w * p[3])));
        v[c][3] = fmaf(r3.x, p[0], fmaf(r3.y, p[1], fmaf(r3.z, p[2], r3.w * p[3])));
        u[c][0] = fmaf(r0.x, p[0], fmaf(r1.x, p[1], fmaf(r2.x, p[2], r3.x * p[3])));
        u[c][1] = fmaf(r0.y, p[0], fmaf(r1.y, p[1], fmaf(r2.y, p[2], r3.y * p[3])));
        u[c][2] = fmaf(r0.z, p[0], fmaf(r1.z, p[1], fmaf(r2.z, p[2], r3.z * p[3])));
        u[c][3] = fmaf(r0.w, p[0], fmaf(r1.w, p[1], fmaf(r2.w, p[2], r3.w * p[3])));
    }

    const size_t bn      = (size_t)BN;
    const size_t blkBase = (size_t)blockIdx.x * (size_t)(TPB * 64);
    const int    sw      = tid & 15;     // float4-granular XOR swizzle key

    // ================= K1 (antisymmetric) =================
#pragma unroll
    for (int c = 0; c < 8; c++) {
#pragma unroll
        for (int d4 = 0; d4 < 2; d4++) {
            float4 row;
            {
                const int d = d4 * 4;
                row.x = 0.5f * (dot4(u[c], v[d + 0]) - dot4(u[d + 0], v[c]));
                row.y = 0.5f * (dot4(u[c], v[d + 1]) - dot4(u[d + 1], v[c]));
                row.z = 0.5f * (dot4(u[c], v[d + 2]) - dot4(u[d + 2], v[c]));
                row.w = 0.5f * (dot4(u[c], v[d + 3]) - dot4(u[d + 3], v[c]));
            }
            const int e4 = c * 2 + d4;                              // 0..15
            *reinterpret_cast<float4*>(&stage[tid * 64 + ((e4 ^ sw) << 2)]) = row;
        }
    }
    __syncthreads();

    {
        float* __restrict__ dst = out + bn + blkBase;
#pragma unroll
        for (int it = 0; it < 16; it++) {
            const int o   = it * (TPB * 4) + tid * 4;   // float offset in block's 8192-float region
            const int tok = o >> 6;
            const int e4  = (o >> 2) & 15;
            const float4 val =
                *reinterpret_cast<const float4*>(&stage[tok * 64 + ((e4 ^ (tok & 15)) << 2)]);
            __stcs(reinterpret_cast<float4*>(&dst[o]), val);
        }
    }
    __syncthreads();

    // ================= K2 (symmetric) =================
#pragma unroll
    for (int c = 0; c < 8; c++) {
#pragma unroll
        for (int d4 = 0; d4 < 2; d4++) {
            float4 row;
            {
                const int d = d4 * 4;
                row.x = 0.5f * (dot4(u[c], v[d + 0]) + dot4(u[d + 0], v[c]));
                row.y = 0.5f * (dot4(u[c], v[d + 1]) + dot4(u[d + 1], v[c]));
                row.z = 0.5f * (dot4(u[c], v[d + 2]) + dot4(u[d + 2], v[c]));
                row.w = 0.5f * (dot4(u[c], v[d + 3]) + dot4(u[d + 3], v[c]));
            }
            const int e4 = c * 2 + d4;
            *reinterpret_cast<float4*>(&stage[tid * 64 + ((e4 ^ sw) << 2)]) = row;
        }
    }
    __syncthreads();

    {
        float* __restrict__ dst = out + bn + bn * 64 + blkBase;
#pragma unroll
        for (int it = 0; it < 16; it++) {
            const int o   = it * (TPB * 4) + tid * 4;
            const int tok = o >> 6;
            const int e4  = (o >> 2) & 15;
            const float4 val =
                *reinterpret_cast<const float4*>(&stage[tok * 64 + ((e4 ^ (tok & 15)) << 2)]);
            __stcs(reinterpret_cast<float4*>(&dst[o]), val);
        }
    }
}

extern "C" void kernel_launch(void* const* d_in, const int* in_sizes, int n_in,
                              void* d_out, int out_size) {
    const float4* psi4   = (const float4*)d_in[0];   // [B, N, 4] f32
    const float4* gamma4 = (const float4*)d_in[1];   // [8, 4, 4] f32
    float* out = (float*)d_out;

    const int BN = in_sizes[0] / 4;                  // 524288 tokens
    const int grid = BN / TPB;                       // 4096, exact

    spinor_bilinears_kernel<<<grid, TPB>>>(psi4, gamma4, out, BN);
}